// round 2
// baseline (speedup 1.0000x reference)
#include <cuda_runtime.h>
#include <cstdint>

// Problem constants
#define BATCH 2
#define SEQ   2048
#define EMB   1024
#define HEADS 16
#define HDIM  64
#define ROWS  (BATCH * SEQ)   // 4096

// ---------------------------------------------------------------------------
// Scratch (device globals; allocation in kernel_launch is forbidden)
// ---------------------------------------------------------------------------
__device__ float g_Q[ROWS * EMB];
__device__ float g_K[ROWS * EMB];
__device__ float g_V[ROWS * EMB];
__device__ float g_C[ROWS * EMB];   // attention context, (b,s) x (h,d) layout

// ---------------------------------------------------------------------------
// NT SGEMM: C[m,n] = sum_k A[m,k] * B[n,k]
// A: MxK row-major, B: NxK row-major, C: MxN row-major.
// Tile 128x128x32, 256 threads, 8x8 per-thread micro-tile.
// M,N % 128 == 0, K % 32 == 0 (true for all call sites here).
// ---------------------------------------------------------------------------
__global__ __launch_bounds__(256) void gemm_nt(
    const float* __restrict__ A, const float* __restrict__ B,
    float* __restrict__ C, int M, int N, int K)
{
    __shared__ float As[32][132];   // [k][m], padded
    __shared__ float Bs[32][132];   // [k][n], padded

    const int tid = threadIdx.x;
    const int bm = blockIdx.y * 128;
    const int bn = blockIdx.x * 128;
    const int tx = tid & 15;        // 0..15
    const int ty = tid >> 4;        // 0..15
    const int m0 = ty * 8;
    const int n0 = tx * 8;

    float acc[8][8];
    #pragma unroll
    for (int i = 0; i < 8; i++)
        #pragma unroll
        for (int j = 0; j < 8; j++) acc[i][j] = 0.f;

    for (int k0 = 0; k0 < K; k0 += 32) {
        // Load 128x32 tiles of A and B (4 float4 per thread each), store k-major.
        #pragma unroll
        for (int u = 0; u < 4; u++) {
            int f   = tid + u * 256;     // float4 index in [0,1024)
            int row = f >> 3;            // 8 float4 per 32-wide row
            int c4  = f & 7;
            float4 a = *(const float4*)&A[(size_t)(bm + row) * K + k0 + c4 * 4];
            As[c4*4+0][row] = a.x; As[c4*4+1][row] = a.y;
            As[c4*4+2][row] = a.z; As[c4*4+3][row] = a.w;
            float4 b = *(const float4*)&B[(size_t)(bn + row) * K + k0 + c4 * 4];
            Bs[c4*4+0][row] = b.x; Bs[c4*4+1][row] = b.y;
            Bs[c4*4+2][row] = b.z; Bs[c4*4+3][row] = b.w;
        }
        __syncthreads();

        #pragma unroll
        for (int k = 0; k < 32; k++) {
            float ar[8], br[8];
            *(float4*)&ar[0] = *(const float4*)&As[k][m0];
            *(float4*)&ar[4] = *(const float4*)&As[k][m0 + 4];
            *(float4*)&br[0] = *(const float4*)&Bs[k][n0];
            *(float4*)&br[4] = *(const float4*)&Bs[k][n0 + 4];
            #pragma unroll
            for (int i = 0; i < 8; i++)
                #pragma unroll
                for (int j = 0; j < 8; j++)
                    acc[i][j] += ar[i] * br[j];
        }
        __syncthreads();
    }

    #pragma unroll
    for (int i = 0; i < 8; i++) {
        float4* crow = (float4*)&C[(size_t)(bm + m0 + i) * N + bn + n0];
        crow[0] = make_float4(acc[i][0], acc[i][1], acc[i][2], acc[i][3]);
        crow[1] = make_float4(acc[i][4], acc[i][5], acc[i][6], acc[i][7]);
    }
}

// ---------------------------------------------------------------------------
// Flash attention (fp32, online softmax). One block = 64 queries of one
// (batch, head). Tiles of 64 kv. D = 64.
// Thread layout: 256 threads = 16x16 (ty,tx).
//   S compute : thread owns S rows i0..i0+3 (i0=ty*4), cols j0..j0+3 (j0=tx*4)
//   O compute : thread owns O rows i0..i0+3, dims d0..d0+3 (d0=tx*4)
// Row softmax stats (m,l) live in registers, replicated across the 16 tx
// lanes that share a ty; reductions via shfl_xor over 16 lanes (lanes of a
// 16-group never cross warp because lane = (ty&1)*16 + tx).
// Kt smem region is reused as P (probabilities) after S is registered.
// NOTE: attention_mask arrives as int32 (harness materializes bool as i32).
// ---------------------------------------------------------------------------
#define FA_PAD 68   // row stride in floats (64 + 4), keeps 16B alignment

__global__ __launch_bounds__(256) void flash_attn(
    const float* __restrict__ Q, const float* __restrict__ K,
    const float* __restrict__ V, const int* __restrict__ mask,
    float* __restrict__ O)
{
    extern __shared__ float sm[];
    float* Qt = sm;                    // [64][FA_PAD], Qt[k][i]
    float* Kt = sm + 64 * FA_PAD;      // [64][FA_PAD], Kt[k][j]; reused as Ps[i][j]
    float* Vs = sm + 2 * 64 * FA_PAD;  // [64][FA_PAD], Vs[j][d]
    float* Ps = Kt;

    const int q0 = blockIdx.x * 64;
    const int h  = blockIdx.y;
    const int b  = blockIdx.z;
    const int tid = threadIdx.x;
    const int tx = tid & 15;
    const int ty = tid >> 4;
    const int i0 = ty * 4;
    const int j0 = tx * 4;

    const size_t base = (size_t)b * SEQ * EMB + h * HDIM;
    const float* Qb = Q + base;
    const float* Kb = K + base;
    const float* Vb = V + base;
    const int* mb = mask + (size_t)b * SEQ;

    // Load Q tile transposed: Qt[k][i] = Q[q0+i][k]
    #pragma unroll
    for (int u = 0; u < 4; u++) {
        int f  = tid + u * 256;  // float4 id in [0,1024)
        int i  = f >> 4;         // 16 float4 per 64-wide row
        int k4 = f & 15;
        float4 q = *(const float4*)&Qb[(size_t)(q0 + i) * EMB + k4 * 4];
        Qt[(k4*4+0) * FA_PAD + i] = q.x;
        Qt[(k4*4+1) * FA_PAD + i] = q.y;
        Qt[(k4*4+2) * FA_PAD + i] = q.z;
        Qt[(k4*4+3) * FA_PAD + i] = q.w;
    }

    float m_i[4], l_i[4], o[4][4];
    #pragma unroll
    for (int r = 0; r < 4; r++) {
        m_i[r] = -1e30f; l_i[r] = 0.f;
        #pragma unroll
        for (int c = 0; c < 4; c++) o[r][c] = 0.f;
    }

    for (int kv0 = 0; kv0 < SEQ; kv0 += 64) {
        __syncthreads();  // previous-iter Ps/Vs readers done before overwrite
        // Load K (transposed) and V (natural) tiles
        #pragma unroll
        for (int u = 0; u < 4; u++) {
            int f  = tid + u * 256;
            int j  = f >> 4;
            int k4 = f & 15;
            float4 kk = *(const float4*)&Kb[(size_t)(kv0 + j) * EMB + k4 * 4];
            Kt[(k4*4+0) * FA_PAD + j] = kk.x;
            Kt[(k4*4+1) * FA_PAD + j] = kk.y;
            Kt[(k4*4+2) * FA_PAD + j] = kk.z;
            Kt[(k4*4+3) * FA_PAD + j] = kk.w;
            float4 vv = *(const float4*)&Vb[(size_t)(kv0 + j) * EMB + k4 * 4];
            *(float4*)&Vs[j * FA_PAD + k4 * 4] = vv;
        }
        __syncthreads();

        // S = Q K^T (this thread: 4x4 tile)
        float s[4][4];
        #pragma unroll
        for (int r = 0; r < 4; r++)
            #pragma unroll
            for (int c = 0; c < 4; c++) s[r][c] = 0.f;

        #pragma unroll 8
        for (int k = 0; k < 64; k++) {
            float qr[4], kr[4];
            *(float4*)qr = *(const float4*)&Qt[k * FA_PAD + i0];
            *(float4*)kr = *(const float4*)&Kt[k * FA_PAD + j0];
            #pragma unroll
            for (int r = 0; r < 4; r++)
                #pragma unroll
                for (int c = 0; c < 4; c++)
                    s[r][c] += qr[r] * kr[c];
        }
        __syncthreads();  // all Kt reads done before Ps overwrites it

        // Mask + scale (mask is int32: nonzero = attend)
        const float scale = 0.125f;  // 1/sqrt(64)
        int mk[4];
        #pragma unroll
        for (int c = 0; c < 4; c++) mk[c] = mb[kv0 + j0 + c];
        #pragma unroll
        for (int r = 0; r < 4; r++)
            #pragma unroll
            for (int c = 0; c < 4; c++)
                s[r][c] = (mk[c] != 0) ? s[r][c] * scale : -1e30f;

        // Online softmax per row (reduce across the 16 tx lanes)
        #pragma unroll
        for (int r = 0; r < 4; r++) {
            float rm = fmaxf(fmaxf(s[r][0], s[r][1]), fmaxf(s[r][2], s[r][3]));
            #pragma unroll
            for (int off = 8; off > 0; off >>= 1)
                rm = fmaxf(rm, __shfl_xor_sync(0xffffffffu, rm, off));
            float m_new = fmaxf(m_i[r], rm);
            float corr  = __expf(m_i[r] - m_new);
            float p[4], rs = 0.f;
            #pragma unroll
            for (int c = 0; c < 4; c++) {
                p[c] = __expf(s[r][c] - m_new);
                rs += p[c];
            }
            *(float4*)&Ps[(i0 + r) * FA_PAD + j0] = *(float4*)p;
            #pragma unroll
            for (int off = 8; off > 0; off >>= 1)
                rs += __shfl_xor_sync(0xffffffffu, rs, off);
            l_i[r] = l_i[r] * corr + rs;
            m_i[r] = m_new;
            #pragma unroll
            for (int c = 0; c < 4; c++) o[r][c] *= corr;
        }
        __syncthreads();

        // O += P * V (this thread: rows i0.., dims j0..)
        #pragma unroll 4
        for (int j = 0; j < 64; j++) {
            float pr[4];
            #pragma unroll
            for (int r = 0; r < 4; r++) pr[r] = Ps[(i0 + r) * FA_PAD + j];
            float vr[4];
            *(float4*)vr = *(const float4*)&Vs[j * FA_PAD + j0];
            #pragma unroll
            for (int r = 0; r < 4; r++)
                #pragma unroll
                for (int c = 0; c < 4; c++)
                    o[r][c] += pr[r] * vr[c];
        }
    }

    // Normalize and write context: O[(b,q0+i)][h*64 + d]
    float* Ob = O + base;
    #pragma unroll
    for (int r = 0; r < 4; r++) {
        float inv = 1.f / l_i[r];
        float4 res = make_float4(o[r][0] * inv, o[r][1] * inv,
                                 o[r][2] * inv, o[r][3] * inv);
        *(float4*)&Ob[(size_t)(q0 + i0 + r) * EMB + j0] = res;
    }
}

// ---------------------------------------------------------------------------
// Launch
// ---------------------------------------------------------------------------
extern "C" void kernel_launch(void* const* d_in, const int* in_sizes, int n_in,
                              void* d_out, int out_size)
{
    const float* x   = (const float*)d_in[0];
    const int*   am  = (const int*)d_in[1];   // bool mask materialized as int32
    const float* Wq  = (const float*)d_in[2];
    const float* Wk  = (const float*)d_in[3];
    const float* Wv  = (const float*)d_in[4];
    const float* Wo  = (const float*)d_in[5];
    float* out       = (float*)d_out;

    float *Qp, *Kp, *Vp, *Cp;
    cudaGetSymbolAddress((void**)&Qp, g_Q);
    cudaGetSymbolAddress((void**)&Kp, g_K);
    cudaGetSymbolAddress((void**)&Vp, g_V);
    cudaGetSymbolAddress((void**)&Cp, g_C);

    const int smem_fa = 3 * 64 * FA_PAD * sizeof(float);  // 52224 B
    cudaFuncSetAttribute(flash_attn, cudaFuncAttributeMaxDynamicSharedMemorySize,
                         smem_fa);

    dim3 gemm_grid(EMB / 128, ROWS / 128);   // (8, 32)
    gemm_nt<<<gemm_grid, 256>>>(x, Wq, Qp, ROWS, EMB, EMB);
    gemm_nt<<<gemm_grid, 256>>>(x, Wk, Kp, ROWS, EMB, EMB);
    gemm_nt<<<gemm_grid, 256>>>(x, Wv, Vp, ROWS, EMB, EMB);

    dim3 fa_grid(SEQ / 64, HEADS, BATCH);    // (32, 16, 2)
    flash_attn<<<fa_grid, 256, smem_fa>>>(Qp, Kp, Vp, am, Cp);

    gemm_nt<<<gemm_grid, 256>>>(Cp, Wo, out, ROWS, EMB, EMB);
}

// round 4
// speedup vs baseline: 1.2560x; 1.2560x over previous
#include <cuda_runtime.h>
#include <cuda_bf16.h>
#include <cstdint>

// Problem constants
#define BATCH 2
#define SEQ   2048
#define EMB   1024
#define HEADS 16
#define HDIM  64
#define ROWS  (BATCH * SEQ)   // 4096
#define GK 1024
#define GN 1024

// ---------------------------------------------------------------------------
// Scratch (device globals; allocation in kernel_launch is forbidden)
// ---------------------------------------------------------------------------
__device__ float g_Q[ROWS * EMB];
__device__ float g_K[ROWS * EMB];
__device__ float g_V[ROWS * EMB];
__device__ float g_C[ROWS * EMB];   // attention context, (b,s) x (h,d) layout

// ---------------------------------------------------------------------------
// Helpers
// ---------------------------------------------------------------------------
__device__ __forceinline__ uint32_t smem_to_u32(const void* p) {
    uint32_t a;
    asm("{ .reg .u64 t; cvta.to.shared.u64 t, %1; cvt.u32.u64 %0, t; }"
        : "=r"(a) : "l"(p));
    return a;
}

__device__ __forceinline__ void ldsm_x4(uint32_t r[4], uint32_t addr) {
    asm volatile("ldmatrix.sync.aligned.m8n8.x4.shared.b16 {%0,%1,%2,%3}, [%4];"
                 : "=r"(r[0]), "=r"(r[1]), "=r"(r[2]), "=r"(r[3]) : "r"(addr));
}

__device__ __forceinline__ void mma_bf16(float c[4],
    uint32_t a0, uint32_t a1, uint32_t a2, uint32_t a3,
    uint32_t b0, uint32_t b1)
{
    asm volatile(
        "mma.sync.aligned.m16n8k16.row.col.f32.bf16.bf16.f32 "
        "{%0,%1,%2,%3}, {%4,%5,%6,%7}, {%8,%9}, {%0,%1,%2,%3};"
        : "+f"(c[0]), "+f"(c[1]), "+f"(c[2]), "+f"(c[3])
        : "r"(a0), "r"(a1), "r"(a2), "r"(a3), "r"(b0), "r"(b1));
}

// split fp32 pair -> packed bf16x2 hi and lo (residual)
__device__ __forceinline__ void split2(float x, float y, uint32_t& hi, uint32_t& lo)
{
    __nv_bfloat16 hx = __float2bfloat16(x);
    __nv_bfloat16 hy = __float2bfloat16(y);
    __nv_bfloat16 lx = __float2bfloat16(x - __bfloat162float(hx));
    __nv_bfloat16 ly = __float2bfloat16(y - __bfloat162float(hy));
    hi = (uint32_t)__bfloat16_as_ushort(hx) | ((uint32_t)__bfloat16_as_ushort(hy) << 16);
    lo = (uint32_t)__bfloat16_as_ushort(lx) | ((uint32_t)__bfloat16_as_ushort(ly) << 16);
}

// ===========================================================================
// HMMA NT GEMM: C[m,n] = sum_k A[m,k] * B[n,k]
// M=4096(blockIdx.y*128), N=1024, K=1024, fp32 in/out.
// Split-bf16 3-pass (AhiBhi + AhiBlo + AloBhi) for ~1e-5 accuracy.
// 256 threads = 8 warps (2m x 4n), warp tile 64x32, K-chunk 32, double buffer.
// smem row stride 80 B (40 bf16) -> conflict-free ldmatrix.
// ===========================================================================
#define LDA_B   80                       // bytes per smem row (40 bf16)
#define OFF_AHI 0
#define OFF_ALO 10240
#define OFF_BHI 20480
#define OFF_BLO 30720
#define STAGE_B 40960
#define GEMM_SMEM (2 * STAGE_B)          // 81920 B

__global__ __launch_bounds__(256, 1) void gemm_tc(
    const float* __restrict__ A, const float* __restrict__ B,
    float* __restrict__ C)
{
    extern __shared__ char smc[];
    const uint32_t sbase = smem_to_u32(smc);
    const int tid  = threadIdx.x;
    const int lane = tid & 31;
    const int w    = tid >> 5;
    const int wm   = w >> 2;       // 0..1
    const int wn   = w & 3;        // 0..3
    const int bn = blockIdx.x * 128;
    const int bm = blockIdx.y * 128;

    float acc[4][4][4];
    #pragma unroll
    for (int i = 0; i < 4; i++)
        #pragma unroll
        for (int j = 0; j < 4; j++)
            #pragma unroll
            for (int q = 0; q < 4; q++) acc[i][j][q] = 0.f;

    // per-thread load mapping: 2 groups of 8 floats from A and from B per chunk
    // idx = tid + u*256 over 512 groups; row = idx/4, kk = (idx%4)*8
    float4 a_st[4], b_st[4];

    // ---- preload chunk 0 into regs
    #pragma unroll
    for (int u = 0; u < 2; ++u) {
        int idx = tid + u * 256;
        int r = idx >> 2, kk = (idx & 3) << 3;
        const float4* pa = (const float4*)&A[(size_t)(bm + r) * GK + kk];
        a_st[2*u] = pa[0]; a_st[2*u+1] = pa[1];
        const float4* pb = (const float4*)&B[(size_t)(bn + r) * GK + kk];
        b_st[2*u] = pb[0]; b_st[2*u+1] = pb[1];
    }

    const int NCH = GK / 32;   // 32 chunks

    for (int it = 0; it < NCH; ++it) {
        const uint32_t stg = (uint32_t)(it & 1) * STAGE_B;

        // ---- convert staged regs -> smem (buffer it&1)
        #pragma unroll
        for (int u = 0; u < 2; ++u) {
            int idx = tid + u * 256;
            int r = idx >> 2, kk = (idx & 3) << 3;
            uint32_t off = (uint32_t)(r * LDA_B + kk * 2);
            uint32_t h0,h1,h2,h3,l0,l1,l2,l3;
            split2(a_st[2*u].x, a_st[2*u].y, h0, l0);
            split2(a_st[2*u].z, a_st[2*u].w, h1, l1);
            split2(a_st[2*u+1].x, a_st[2*u+1].y, h2, l2);
            split2(a_st[2*u+1].z, a_st[2*u+1].w, h3, l3);
            *(uint4*)(smc + stg + OFF_AHI + off) = make_uint4(h0,h1,h2,h3);
            *(uint4*)(smc + stg + OFF_ALO + off) = make_uint4(l0,l1,l2,l3);
            split2(b_st[2*u].x, b_st[2*u].y, h0, l0);
            split2(b_st[2*u].z, b_st[2*u].w, h1, l1);
            split2(b_st[2*u+1].x, b_st[2*u+1].y, h2, l2);
            split2(b_st[2*u+1].z, b_st[2*u+1].w, h3, l3);
            *(uint4*)(smc + stg + OFF_BHI + off) = make_uint4(h0,h1,h2,h3);
            *(uint4*)(smc + stg + OFF_BLO + off) = make_uint4(l0,l1,l2,l3);
        }
        __syncthreads();

        // ---- issue next chunk's global loads (latency hidden under MMAs)
        if (it + 1 < NCH) {
            const int k0 = (it + 1) * 32;
            #pragma unroll
            for (int u = 0; u < 2; ++u) {
                int idx = tid + u * 256;
                int r = idx >> 2, kk = (idx & 3) << 3;
                const float4* pa = (const float4*)&A[(size_t)(bm + r) * GK + k0 + kk];
                a_st[2*u] = pa[0]; a_st[2*u+1] = pa[1];
                const float4* pb = (const float4*)&B[(size_t)(bn + r) * GK + k0 + kk];
                b_st[2*u] = pb[0]; b_st[2*u+1] = pb[1];
            }
        }

        // ---- compute on buffer it&1
        const uint32_t sb = sbase + stg;
        #pragma unroll
        for (int ks = 0; ks < 2; ++ks) {
            uint32_t ah[4][4], al[4][4], bh[2][4], bl[2][4];
            const uint32_t kcol = (uint32_t)((ks * 16 + ((lane >> 4) << 3)) * 2);
            const int arow = wm * 64 + (lane & 15);
            #pragma unroll
            for (int ms = 0; ms < 4; ++ms) {
                uint32_t off = (uint32_t)((arow + ms * 16) * LDA_B) + kcol;
                ldsm_x4(ah[ms], sb + OFF_AHI + off);
                ldsm_x4(al[ms], sb + OFF_ALO + off);
            }
            const int brow = wn * 32 + (lane & 15);
            #pragma unroll
            for (int pr = 0; pr < 2; ++pr) {
                uint32_t off = (uint32_t)((brow + pr * 16) * LDA_B) + kcol;
                ldsm_x4(bh[pr], sb + OFF_BHI + off);
                ldsm_x4(bl[pr], sb + OFF_BLO + off);
            }
            #pragma unroll
            for (int ms = 0; ms < 4; ++ms)
                #pragma unroll
                for (int ns = 0; ns < 4; ++ns) {
                    const int pr = ns >> 1, od = ns & 1;
                    mma_bf16(acc[ms][ns], ah[ms][0], ah[ms][1], ah[ms][2], ah[ms][3],
                             bh[pr][od], bh[pr][od + 2]);
                    mma_bf16(acc[ms][ns], ah[ms][0], ah[ms][1], ah[ms][2], ah[ms][3],
                             bl[pr][od], bl[pr][od + 2]);
                    mma_bf16(acc[ms][ns], al[ms][0], al[ms][1], al[ms][2], al[ms][3],
                             bh[pr][od], bh[pr][od + 2]);
                }
        }
        __syncthreads();
    }

    // ---- epilogue: standard m16n8 accumulator mapping
    #pragma unroll
    for (int ms = 0; ms < 4; ++ms) {
        const int row0 = bm + wm * 64 + ms * 16 + (lane >> 2);
        #pragma unroll
        for (int ns = 0; ns < 4; ++ns) {
            const int col = bn + wn * 32 + ns * 8 + (lane & 3) * 2;
            *(float2*)&C[(size_t)row0 * GN + col] =
                make_float2(acc[ms][ns][0], acc[ms][ns][1]);
            *(float2*)&C[(size_t)(row0 + 8) * GN + col] =
                make_float2(acc[ms][ns][2], acc[ms][ns][3]);
        }
    }
}

// ---------------------------------------------------------------------------
// Flash attention (fp32, online softmax) — unchanged (passing, rel_err 1.4e-6)
// ---------------------------------------------------------------------------
#define FA_PAD 68   // row stride in floats (64 + 4), keeps 16B alignment

__global__ __launch_bounds__(256) void flash_attn(
    const float* __restrict__ Q, const float* __restrict__ K,
    const float* __restrict__ V, const int* __restrict__ mask,
    float* __restrict__ O)
{
    extern __shared__ float sm[];
    float* Qt = sm;                    // [64][FA_PAD], Qt[k][i]
    float* Kt = sm + 64 * FA_PAD;      // [64][FA_PAD], Kt[k][j]; reused as Ps[i][j]
    float* Vs = sm + 2 * 64 * FA_PAD;  // [64][FA_PAD], Vs[j][d]
    float* Ps = Kt;

    const int q0 = blockIdx.x * 64;
    const int h  = blockIdx.y;
    const int b  = blockIdx.z;
    const int tid = threadIdx.x;
    const int tx = tid & 15;
    const int ty = tid >> 4;
    const int i0 = ty * 4;
    const int j0 = tx * 4;

    const size_t base = (size_t)b * SEQ * EMB + h * HDIM;
    const float* Qb = Q + base;
    const float* Kb = K + base;
    const float* Vb = V + base;
    const int* mb = mask + (size_t)b * SEQ;

    #pragma unroll
    for (int u = 0; u < 4; u++) {
        int f  = tid + u * 256;
        int i  = f >> 4;
        int k4 = f & 15;
        float4 q = *(const float4*)&Qb[(size_t)(q0 + i) * EMB + k4 * 4];
        Qt[(k4*4+0) * FA_PAD + i] = q.x;
        Qt[(k4*4+1) * FA_PAD + i] = q.y;
        Qt[(k4*4+2) * FA_PAD + i] = q.z;
        Qt[(k4*4+3) * FA_PAD + i] = q.w;
    }

    float m_i[4], l_i[4], o[4][4];
    #pragma unroll
    for (int r = 0; r < 4; r++) {
        m_i[r] = -1e30f; l_i[r] = 0.f;
        #pragma unroll
        for (int c = 0; c < 4; c++) o[r][c] = 0.f;
    }

    for (int kv0 = 0; kv0 < SEQ; kv0 += 64) {
        __syncthreads();
        #pragma unroll
        for (int u = 0; u < 4; u++) {
            int f  = tid + u * 256;
            int j  = f >> 4;
            int k4 = f & 15;
            float4 kk = *(const float4*)&Kb[(size_t)(kv0 + j) * EMB + k4 * 4];
            Kt[(k4*4+0) * FA_PAD + j] = kk.x;
            Kt[(k4*4+1) * FA_PAD + j] = kk.y;
            Kt[(k4*4+2) * FA_PAD + j] = kk.z;
            Kt[(k4*4+3) * FA_PAD + j] = kk.w;
            float4 vv = *(const float4*)&Vb[(size_t)(kv0 + j) * EMB + k4 * 4];
            *(float4*)&Vs[j * FA_PAD + k4 * 4] = vv;
        }
        __syncthreads();

        float s[4][4];
        #pragma unroll
        for (int r = 0; r < 4; r++)
            #pragma unroll
            for (int c = 0; c < 4; c++) s[r][c] = 0.f;

        #pragma unroll 8
        for (int k = 0; k < 64; k++) {
            float qr[4], kr[4];
            *(float4*)qr = *(const float4*)&Qt[k * FA_PAD + i0];
            *(float4*)kr = *(const float4*)&Kt[k * FA_PAD + j0];
            #pragma unroll
            for (int r = 0; r < 4; r++)
                #pragma unroll
                for (int c = 0; c < 4; c++)
                    s[r][c] += qr[r] * kr[c];
        }
        __syncthreads();

        const float scale = 0.125f;  // 1/sqrt(64)
        int mk[4];
        #pragma unroll
        for (int c = 0; c < 4; c++) mk[c] = mb[kv0 + j0 + c];
        #pragma unroll
        for (int r = 0; r < 4; r++)
            #pragma unroll
            for (int c = 0; c < 4; c++)
                s[r][c] = (mk[c] != 0) ? s[r][c] * scale : -1e30f;

        #pragma unroll
        for (int r = 0; r < 4; r++) {
            float rm = fmaxf(fmaxf(s[r][0], s[r][1]), fmaxf(s[r][2], s[r][3]));
            #pragma unroll
            for (int off = 8; off > 0; off >>= 1)
                rm = fmaxf(rm, __shfl_xor_sync(0xffffffffu, rm, off));
            float m_new = fmaxf(m_i[r], rm);
            float corr  = __expf(m_i[r] - m_new);
            float p[4], rs = 0.f;
            #pragma unroll
            for (int c = 0; c < 4; c++) {
                p[c] = __expf(s[r][c] - m_new);
                rs += p[c];
            }
            *(float4*)&Ps[(i0 + r) * FA_PAD + j0] = *(float4*)p;
            #pragma unroll
            for (int off = 8; off > 0; off >>= 1)
                rs += __shfl_xor_sync(0xffffffffu, rs, off);
            l_i[r] = l_i[r] * corr + rs;
            m_i[r] = m_new;
            #pragma unroll
            for (int c = 0; c < 4; c++) o[r][c] *= corr;
        }
        __syncthreads();

        #pragma unroll 4
        for (int j = 0; j < 64; j++) {
            float pr[4];
            #pragma unroll
            for (int r = 0; r < 4; r++) pr[r] = Ps[(i0 + r) * FA_PAD + j];
            float vr[4];
            *(float4*)vr = *(const float4*)&Vs[j * FA_PAD + j0];
            #pragma unroll
            for (int r = 0; r < 4; r++)
                #pragma unroll
                for (int c = 0; c < 4; c++)
                    o[r][c] += pr[r] * vr[c];
        }
    }

    float* Ob = O + base;
    #pragma unroll
    for (int r = 0; r < 4; r++) {
        float inv = 1.f / l_i[r];
        float4 res = make_float4(o[r][0] * inv, o[r][1] * inv,
                                 o[r][2] * inv, o[r][3] * inv);
        *(float4*)&Ob[(size_t)(q0 + i0 + r) * EMB + j0] = res;
    }
}

// ---------------------------------------------------------------------------
// Launch
// ---------------------------------------------------------------------------
extern "C" void kernel_launch(void* const* d_in, const int* in_sizes, int n_in,
                              void* d_out, int out_size)
{
    const float* x   = (const float*)d_in[0];
    const int*   am  = (const int*)d_in[1];   // bool mask materialized as int32
    const float* Wq  = (const float*)d_in[2];
    const float* Wk  = (const float*)d_in[3];
    const float* Wv  = (const float*)d_in[4];
    const float* Wo  = (const float*)d_in[5];
    float* out       = (float*)d_out;

    float *Qp, *Kp, *Vp, *Cp;
    cudaGetSymbolAddress((void**)&Qp, g_Q);
    cudaGetSymbolAddress((void**)&Kp, g_K);
    cudaGetSymbolAddress((void**)&Vp, g_V);
    cudaGetSymbolAddress((void**)&Cp, g_C);

    cudaFuncSetAttribute(gemm_tc, cudaFuncAttributeMaxDynamicSharedMemorySize,
                         GEMM_SMEM);
    const int smem_fa = 3 * 64 * FA_PAD * sizeof(float);  // 52224 B
    cudaFuncSetAttribute(flash_attn, cudaFuncAttributeMaxDynamicSharedMemorySize,
                         smem_fa);

    dim3 gemm_grid(GN / 128, ROWS / 128);    // (8, 32)
    gemm_tc<<<gemm_grid, 256, GEMM_SMEM>>>(x, Wq, Qp);
    gemm_tc<<<gemm_grid, 256, GEMM_SMEM>>>(x, Wk, Kp);
    gemm_tc<<<gemm_grid, 256, GEMM_SMEM>>>(x, Wv, Vp);

    dim3 fa_grid(SEQ / 64, HEADS, BATCH);    // (32, 16, 2)
    flash_attn<<<fa_grid, 256, smem_fa>>>(Qp, Kp, Vp, am, Cp);

    gemm_tc<<<gemm_grid, 256, GEMM_SMEM>>>(Cp, Wo, out);
}

// round 5
// speedup vs baseline: 1.8748x; 1.4927x over previous
#include <cuda_runtime.h>
#include <cuda_bf16.h>
#include <cstdint>

// Problem constants
#define BATCH 2
#define SEQ   2048
#define EMB   1024
#define HEADS 16
#define HDIM  64
#define ROWS  (BATCH * SEQ)   // 4096
#define GK 1024
#define GN 1024

// ---------------------------------------------------------------------------
// Scratch (device globals; allocation in kernel_launch is forbidden)
// ---------------------------------------------------------------------------
__device__ float g_Q[ROWS * EMB];
__device__ float g_K[ROWS * EMB];
__device__ float g_V[ROWS * EMB];
__device__ float g_C[ROWS * EMB];   // attention context, (b,s) x (h,d) layout

// ---------------------------------------------------------------------------
// Helpers
// ---------------------------------------------------------------------------
__device__ __forceinline__ uint32_t smem_to_u32(const void* p) {
    uint32_t a;
    asm("{ .reg .u64 t; cvta.to.shared.u64 t, %1; cvt.u32.u64 %0, t; }"
        : "=r"(a) : "l"(p));
    return a;
}

__device__ __forceinline__ void ldsm_x4(uint32_t r[4], uint32_t addr) {
    asm volatile("ldmatrix.sync.aligned.m8n8.x4.shared.b16 {%0,%1,%2,%3}, [%4];"
                 : "=r"(r[0]), "=r"(r[1]), "=r"(r[2]), "=r"(r[3]) : "r"(addr));
}

// transposed ldmatrix: loads 8x8 b16 tiles transposed (for B from [k][n] storage)
__device__ __forceinline__ void ldsm_x4_t(uint32_t r[4], uint32_t addr) {
    asm volatile("ldmatrix.sync.aligned.m8n8.x4.trans.shared.b16 {%0,%1,%2,%3}, [%4];"
                 : "=r"(r[0]), "=r"(r[1]), "=r"(r[2]), "=r"(r[3]) : "r"(addr));
}

__device__ __forceinline__ void mma_bf16(float c[4],
    uint32_t a0, uint32_t a1, uint32_t a2, uint32_t a3,
    uint32_t b0, uint32_t b1)
{
    asm volatile(
        "mma.sync.aligned.m16n8k16.row.col.f32.bf16.bf16.f32 "
        "{%0,%1,%2,%3}, {%4,%5,%6,%7}, {%8,%9}, {%0,%1,%2,%3};"
        : "+f"(c[0]), "+f"(c[1]), "+f"(c[2]), "+f"(c[3])
        : "r"(a0), "r"(a1), "r"(a2), "r"(a3), "r"(b0), "r"(b1));
}

// split fp32 pair -> packed bf16x2 hi and lo (residual)
__device__ __forceinline__ void split2(float x, float y, uint32_t& hi, uint32_t& lo)
{
    __nv_bfloat16 hx = __float2bfloat16(x);
    __nv_bfloat16 hy = __float2bfloat16(y);
    __nv_bfloat16 lx = __float2bfloat16(x - __bfloat162float(hx));
    __nv_bfloat16 ly = __float2bfloat16(y - __bfloat162float(hy));
    hi = (uint32_t)__bfloat16_as_ushort(hx) | ((uint32_t)__bfloat16_as_ushort(hy) << 16);
    lo = (uint32_t)__bfloat16_as_ushort(lx) | ((uint32_t)__bfloat16_as_ushort(ly) << 16);
}

// convert 8 fp32 (two float4) -> uint4 of bf16-hi pairs and uint4 of bf16-lo pairs
__device__ __forceinline__ void cvt16(const float4& a, const float4& b,
                                      uint4& hi, uint4& lo)
{
    uint32_t h0,h1,h2,h3,l0,l1,l2,l3;
    split2(a.x, a.y, h0, l0); split2(a.z, a.w, h1, l1);
    split2(b.x, b.y, h2, l2); split2(b.z, b.w, h3, l3);
    hi = make_uint4(h0,h1,h2,h3);
    lo = make_uint4(l0,l1,l2,l3);
}

// ===========================================================================
// HMMA NT GEMM (unchanged from R4, passing): C[m,n] = sum_k A[m,k]*B[n,k]
// ===========================================================================
#define LDA_B   80
#define OFF_AHI 0
#define OFF_ALO 10240
#define OFF_BHI 20480
#define OFF_BLO 30720
#define STAGE_B 40960
#define GEMM_SMEM (2 * STAGE_B)          // 81920 B

__global__ __launch_bounds__(256, 1) void gemm_tc(
    const float* __restrict__ A, const float* __restrict__ B,
    float* __restrict__ C)
{
    extern __shared__ char smc[];
    const uint32_t sbase = smem_to_u32(smc);
    const int tid  = threadIdx.x;
    const int lane = tid & 31;
    const int w    = tid >> 5;
    const int wm   = w >> 2;
    const int wn   = w & 3;
    const int bn = blockIdx.x * 128;
    const int bm = blockIdx.y * 128;

    float acc[4][4][4];
    #pragma unroll
    for (int i = 0; i < 4; i++)
        #pragma unroll
        for (int j = 0; j < 4; j++)
            #pragma unroll
            for (int q = 0; q < 4; q++) acc[i][j][q] = 0.f;

    float4 a_st[4], b_st[4];

    #pragma unroll
    for (int u = 0; u < 2; ++u) {
        int idx = tid + u * 256;
        int r = idx >> 2, kk = (idx & 3) << 3;
        const float4* pa = (const float4*)&A[(size_t)(bm + r) * GK + kk];
        a_st[2*u] = pa[0]; a_st[2*u+1] = pa[1];
        const float4* pb = (const float4*)&B[(size_t)(bn + r) * GK + kk];
        b_st[2*u] = pb[0]; b_st[2*u+1] = pb[1];
    }

    const int NCH = GK / 32;

    for (int it = 0; it < NCH; ++it) {
        const uint32_t stg = (uint32_t)(it & 1) * STAGE_B;

        #pragma unroll
        for (int u = 0; u < 2; ++u) {
            int idx = tid + u * 256;
            int r = idx >> 2, kk = (idx & 3) << 3;
            uint32_t off = (uint32_t)(r * LDA_B + kk * 2);
            uint4 hi, lo;
            cvt16(a_st[2*u], a_st[2*u+1], hi, lo);
            *(uint4*)(smc + stg + OFF_AHI + off) = hi;
            *(uint4*)(smc + stg + OFF_ALO + off) = lo;
            cvt16(b_st[2*u], b_st[2*u+1], hi, lo);
            *(uint4*)(smc + stg + OFF_BHI + off) = hi;
            *(uint4*)(smc + stg + OFF_BLO + off) = lo;
        }
        __syncthreads();

        if (it + 1 < NCH) {
            const int k0 = (it + 1) * 32;
            #pragma unroll
            for (int u = 0; u < 2; ++u) {
                int idx = tid + u * 256;
                int r = idx >> 2, kk = (idx & 3) << 3;
                const float4* pa = (const float4*)&A[(size_t)(bm + r) * GK + k0 + kk];
                a_st[2*u] = pa[0]; a_st[2*u+1] = pa[1];
                const float4* pb = (const float4*)&B[(size_t)(bn + r) * GK + k0 + kk];
                b_st[2*u] = pb[0]; b_st[2*u+1] = pb[1];
            }
        }

        const uint32_t sb = sbase + stg;
        #pragma unroll
        for (int ks = 0; ks < 2; ++ks) {
            uint32_t ah[4][4], al[4][4], bh[2][4], bl[2][4];
            const uint32_t kcol = (uint32_t)((ks * 16 + ((lane >> 4) << 3)) * 2);
            const int arow = wm * 64 + (lane & 15);
            #pragma unroll
            for (int ms = 0; ms < 4; ++ms) {
                uint32_t off = (uint32_t)((arow + ms * 16) * LDA_B) + kcol;
                ldsm_x4(ah[ms], sb + OFF_AHI + off);
                ldsm_x4(al[ms], sb + OFF_ALO + off);
            }
            const int brow = wn * 32 + (lane & 15);
            #pragma unroll
            for (int pr = 0; pr < 2; ++pr) {
                uint32_t off = (uint32_t)((brow + pr * 16) * LDA_B) + kcol;
                ldsm_x4(bh[pr], sb + OFF_BHI + off);
                ldsm_x4(bl[pr], sb + OFF_BLO + off);
            }
            #pragma unroll
            for (int ms = 0; ms < 4; ++ms)
                #pragma unroll
                for (int ns = 0; ns < 4; ++ns) {
                    const int pr = ns >> 1, od = ns & 1;
                    mma_bf16(acc[ms][ns], ah[ms][0], ah[ms][1], ah[ms][2], ah[ms][3],
                             bh[pr][od], bh[pr][od + 2]);
                    mma_bf16(acc[ms][ns], ah[ms][0], ah[ms][1], ah[ms][2], ah[ms][3],
                             bl[pr][od], bl[pr][od + 2]);
                    mma_bf16(acc[ms][ns], al[ms][0], al[ms][1], al[ms][2], al[ms][3],
                             bh[pr][od], bh[pr][od + 2]);
                }
        }
        __syncthreads();
    }

    #pragma unroll
    for (int ms = 0; ms < 4; ++ms) {
        const int row0 = bm + wm * 64 + ms * 16 + (lane >> 2);
        #pragma unroll
        for (int ns = 0; ns < 4; ++ns) {
            const int col = bn + wn * 32 + ns * 8 + (lane & 3) * 2;
            *(float2*)&C[(size_t)row0 * GN + col] =
                make_float2(acc[ms][ns][0], acc[ms][ns][1]);
            *(float2*)&C[(size_t)(row0 + 8) * GN + col] =
                make_float2(acc[ms][ns][2], acc[ms][ns][3]);
        }
    }
}

// ===========================================================================
// Tensor-core flash attention (split-bf16, online softmax).
// Block = 128 queries of one (b,h); 8 warps, warp owns 16 q rows.
// KV tiles of 64. D = 64. mask arrives as int32.
// smem: Q staging (hi/lo) reused by per-tile K/V hi/lo buffers. stride 144 B.
// ===========================================================================
#define FS_LD   144                    // smem row stride bytes (9*16)
#define FQ_HI   0
#define FQ_LO   (128 * FS_LD)          // 18432
#define FK_HI   0
#define FK_LO   (64 * FS_LD)           // 9216
#define FV_HI   (2 * 64 * FS_LD)       // 18432
#define FV_LO   (3 * 64 * FS_LD)       // 27648
#define FBIAS   (4 * 64 * FS_LD)       // 36864
#define FA_SMEM (FBIAS + 64 * 4)       // 37120 B

__global__ __launch_bounds__(256) void flash_tc(
    const float* __restrict__ Q, const float* __restrict__ K,
    const float* __restrict__ V, const int* __restrict__ mask,
    float* __restrict__ O)
{
    extern __shared__ char smc[];
    const uint32_t sbase = smem_to_u32(smc);
    const int tid  = threadIdx.x;
    const int lane = tid & 31;
    const int w    = tid >> 5;
    const int q0 = blockIdx.x * 128;
    const int h  = blockIdx.y;
    const int b  = blockIdx.z;

    const size_t base = (size_t)b * SEQ * EMB + h * HDIM;
    const float* Qb = Q + base;
    const float* Kb = K + base;
    const float* Vb = V + base;
    const int* mb = mask + (size_t)b * SEQ;

    // ---- stage Q tile (128 x 64) as bf16 hi/lo in smem
    {
        const int row = tid >> 1;
        const int d0  = (tid & 1) * 32;
        const float4* pq = (const float4*)&Qb[(size_t)(q0 + row) * EMB + d0];
        #pragma unroll
        for (int sg = 0; sg < 4; ++sg) {
            uint4 hi, lo;
            cvt16(pq[2*sg], pq[2*sg+1], hi, lo);
            uint32_t off = (uint32_t)(row * FS_LD + d0 * 2 + sg * 16);
            *(uint4*)(smc + FQ_HI + off) = hi;
            *(uint4*)(smc + FQ_LO + off) = lo;
        }
    }
    __syncthreads();

    // ---- extract Q fragments (register-resident for whole KV loop)
    uint32_t qh[4][4], ql[4][4];
    #pragma unroll
    for (int ks = 0; ks < 4; ++ks) {
        uint32_t off = (uint32_t)((w * 16 + (lane & 15)) * FS_LD +
                                  (ks * 16 + ((lane >> 4) << 3)) * 2);
        ldsm_x4(qh[ks], sbase + FQ_HI + off);
        ldsm_x4(ql[ks], sbase + FQ_LO + off);
    }

    float oacc[8][4];
    #pragma unroll
    for (int j = 0; j < 8; ++j)
        #pragma unroll
        for (int q = 0; q < 4; ++q) oacc[j][q] = 0.f;
    float mrow0 = -1e30f, mrow1 = -1e30f, lrow0 = 0.f, lrow1 = 0.f;

    for (int kv0 = 0; kv0 < SEQ; kv0 += 64) {
        __syncthreads();   // previous iter's ldmatrix done (also covers Q extract)

        // ---- load K,V tiles (64 x 64 fp32) -> bf16 hi/lo smem
        {
            const int kvr = tid >> 2;
            const int d0  = (tid & 3) << 4;
            const float4* pk = (const float4*)&Kb[(size_t)(kv0 + kvr) * EMB + d0];
            const float4* pv = (const float4*)&Vb[(size_t)(kv0 + kvr) * EMB + d0];
            #pragma unroll
            for (int sg = 0; sg < 2; ++sg) {
                uint4 hi, lo;
                uint32_t off = (uint32_t)(kvr * FS_LD + d0 * 2 + sg * 16);
                cvt16(pk[2*sg], pk[2*sg+1], hi, lo);
                *(uint4*)(smc + FK_HI + off) = hi;
                *(uint4*)(smc + FK_LO + off) = lo;
                cvt16(pv[2*sg], pv[2*sg+1], hi, lo);
                *(uint4*)(smc + FV_HI + off) = hi;
                *(uint4*)(smc + FV_LO + off) = lo;
            }
            if (tid < 64)
                *(float*)(smc + FBIAS + tid * 4) = mb[kv0 + tid] ? 0.f : -1e30f;
        }
        __syncthreads();

        // ---- S = Q K^T : 8 n-tiles of 8 kv, split-bf16 3-pass
        float s[8][4];
        #pragma unroll
        for (int j = 0; j < 8; ++j)
            #pragma unroll
            for (int q = 0; q < 4; ++q) s[j][q] = 0.f;

        #pragma unroll
        for (int pr = 0; pr < 4; ++pr) {
            #pragma unroll
            for (int ks = 0; ks < 4; ++ks) {
                uint32_t kh[4], kl[4];
                uint32_t off = (uint32_t)(((lane & 15) + pr * 16) * FS_LD +
                                          (ks * 16 + ((lane >> 4) << 3)) * 2);
                ldsm_x4(kh, sbase + FK_HI + off);
                ldsm_x4(kl, sbase + FK_LO + off);
                #pragma unroll
                for (int od = 0; od < 2; ++od) {
                    const int j = pr * 2 + od;
                    mma_bf16(s[j], qh[ks][0], qh[ks][1], qh[ks][2], qh[ks][3],
                             kh[od], kh[od + 2]);
                    mma_bf16(s[j], qh[ks][0], qh[ks][1], qh[ks][2], qh[ks][3],
                             kl[od], kl[od + 2]);
                    mma_bf16(s[j], ql[ks][0], ql[ks][1], ql[ks][2], ql[ks][3],
                             kh[od], kh[od + 2]);
                }
            }
        }

        // ---- scale + mask bias
        const float scale = 0.125f;   // 1/sqrt(64)
        #pragma unroll
        for (int j = 0; j < 8; ++j) {
            float2 bs = *(float2*)(smc + FBIAS + (j * 8 + (lane & 3) * 2) * 4);
            s[j][0] = s[j][0] * scale + bs.x;
            s[j][1] = s[j][1] * scale + bs.y;
            s[j][2] = s[j][2] * scale + bs.x;
            s[j][3] = s[j][3] * scale + bs.y;
        }

        // ---- online softmax (rows live on quads: shfl_xor 1,2)
        float rm0 = -1e30f, rm1 = -1e30f;
        #pragma unroll
        for (int j = 0; j < 8; ++j) {
            rm0 = fmaxf(rm0, fmaxf(s[j][0], s[j][1]));
            rm1 = fmaxf(rm1, fmaxf(s[j][2], s[j][3]));
        }
        rm0 = fmaxf(rm0, __shfl_xor_sync(0xffffffffu, rm0, 1));
        rm0 = fmaxf(rm0, __shfl_xor_sync(0xffffffffu, rm0, 2));
        rm1 = fmaxf(rm1, __shfl_xor_sync(0xffffffffu, rm1, 1));
        rm1 = fmaxf(rm1, __shfl_xor_sync(0xffffffffu, rm1, 2));
        const float mn0 = fmaxf(mrow0, rm0);
        const float mn1 = fmaxf(mrow1, rm1);
        const float corr0 = __expf(mrow0 - mn0);
        const float corr1 = __expf(mrow1 - mn1);
        float sum0 = 0.f, sum1 = 0.f;
        #pragma unroll
        for (int j = 0; j < 8; ++j) {
            s[j][0] = __expf(s[j][0] - mn0); sum0 += s[j][0];
            s[j][1] = __expf(s[j][1] - mn0); sum0 += s[j][1];
            s[j][2] = __expf(s[j][2] - mn1); sum1 += s[j][2];
            s[j][3] = __expf(s[j][3] - mn1); sum1 += s[j][3];
        }
        sum0 += __shfl_xor_sync(0xffffffffu, sum0, 1);
        sum0 += __shfl_xor_sync(0xffffffffu, sum0, 2);
        sum1 += __shfl_xor_sync(0xffffffffu, sum1, 1);
        sum1 += __shfl_xor_sync(0xffffffffu, sum1, 2);
        lrow0 = lrow0 * corr0 + sum0;
        lrow1 = lrow1 * corr1 + sum1;
        mrow0 = mn0; mrow1 = mn1;
        #pragma unroll
        for (int j = 0; j < 8; ++j) {
            oacc[j][0] *= corr0; oacc[j][1] *= corr0;
            oacc[j][2] *= corr1; oacc[j][3] *= corr1;
        }

        // ---- O += P V : P fragments built directly from S registers;
        //      V fragments via ldmatrix.trans on [kv][d] storage
        #pragma unroll
        for (int kk = 0; kk < 4; ++kk) {
            uint32_t ah[4], al[4];
            split2(s[2*kk][0],   s[2*kk][1],   ah[0], al[0]);
            split2(s[2*kk][2],   s[2*kk][3],   ah[1], al[1]);
            split2(s[2*kk+1][0], s[2*kk+1][1], ah[2], al[2]);
            split2(s[2*kk+1][2], s[2*kk+1][3], ah[3], al[3]);
            #pragma unroll
            for (int g = 0; g < 4; ++g) {
                uint32_t vh[4], vl[4];
                uint32_t voff = (uint32_t)(
                    (kk * 16 + ((lane >> 4) << 3) + (lane & 7)) * FS_LD +
                    g * 32 + ((lane >> 3) & 1) * 16);
                ldsm_x4_t(vh, sbase + FV_HI + voff);
                ldsm_x4_t(vl, sbase + FV_LO + voff);
                #pragma unroll
                for (int od = 0; od < 2; ++od) {
                    const int j = g * 2 + od;
                    mma_bf16(oacc[j], ah[0], ah[1], ah[2], ah[3], vh[od], vh[od + 2]);
                    mma_bf16(oacc[j], ah[0], ah[1], ah[2], ah[3], vl[od], vl[od + 2]);
                    mma_bf16(oacc[j], al[0], al[1], al[2], al[3], vh[od], vh[od + 2]);
                }
            }
        }
    }

    // ---- normalize + write context
    const float inv0 = 1.f / lrow0;
    const float inv1 = 1.f / lrow1;
    float* Ob = O + base;
    const int r0 = q0 + w * 16 + (lane >> 2);
    #pragma unroll
    for (int j = 0; j < 8; ++j) {
        const int col = j * 8 + (lane & 3) * 2;
        *(float2*)&Ob[(size_t)r0 * EMB + col] =
            make_float2(oacc[j][0] * inv0, oacc[j][1] * inv0);
        *(float2*)&Ob[(size_t)(r0 + 8) * EMB + col] =
            make_float2(oacc[j][2] * inv1, oacc[j][3] * inv1);
    }
}

// ---------------------------------------------------------------------------
// Launch
// ---------------------------------------------------------------------------
extern "C" void kernel_launch(void* const* d_in, const int* in_sizes, int n_in,
                              void* d_out, int out_size)
{
    const float* x   = (const float*)d_in[0];
    const int*   am  = (const int*)d_in[1];   // bool mask materialized as int32
    const float* Wq  = (const float*)d_in[2];
    const float* Wk  = (const float*)d_in[3];
    const float* Wv  = (const float*)d_in[4];
    const float* Wo  = (const float*)d_in[5];
    float* out       = (float*)d_out;

    float *Qp, *Kp, *Vp, *Cp;
    cudaGetSymbolAddress((void**)&Qp, g_Q);
    cudaGetSymbolAddress((void**)&Kp, g_K);
    cudaGetSymbolAddress((void**)&Vp, g_V);
    cudaGetSymbolAddress((void**)&Cp, g_C);

    cudaFuncSetAttribute(gemm_tc, cudaFuncAttributeMaxDynamicSharedMemorySize,
                         GEMM_SMEM);
    cudaFuncSetAttribute(flash_tc, cudaFuncAttributeMaxDynamicSharedMemorySize,
                         FA_SMEM);

    dim3 gemm_grid(GN / 128, ROWS / 128);    // (8, 32)
    gemm_tc<<<gemm_grid, 256, GEMM_SMEM>>>(x, Wq, Qp);
    gemm_tc<<<gemm_grid, 256, GEMM_SMEM>>>(x, Wk, Kp);
    gemm_tc<<<gemm_grid, 256, GEMM_SMEM>>>(x, Wv, Vp);

    dim3 fa_grid(SEQ / 128, HEADS, BATCH);   // (16, 16, 2)
    flash_tc<<<fa_grid, 256, FA_SMEM>>>(Qp, Kp, Vp, am, Cp);

    gemm_tc<<<gemm_grid, 256, GEMM_SMEM>>>(Cp, Wo, out);
}

// round 6
// speedup vs baseline: 2.4439x; 1.3036x over previous
#include <cuda_runtime.h>
#include <cuda_bf16.h>
#include <cstdint>

// Problem constants
#define BATCH 2
#define SEQ   2048
#define EMB   1024
#define HEADS 16
#define HDIM  64
#define ROWS  (BATCH * SEQ)   // 4096
#define GK 1024
#define GN 1024

// ---------------------------------------------------------------------------
// Scratch (device globals; allocation in kernel_launch is forbidden)
// ---------------------------------------------------------------------------
__device__ float g_Q[ROWS * EMB];
__device__ float g_K[ROWS * EMB];
__device__ float g_V[ROWS * EMB];
__device__ float g_C[ROWS * EMB];   // attention context, (b,s) x (h,d) layout

// ---------------------------------------------------------------------------
// Helpers
// ---------------------------------------------------------------------------
__device__ __forceinline__ uint32_t smem_to_u32(const void* p) {
    uint32_t a;
    asm("{ .reg .u64 t; cvta.to.shared.u64 t, %1; cvt.u32.u64 %0, t; }"
        : "=r"(a) : "l"(p));
    return a;
}

__device__ __forceinline__ void ldsm_x4(uint32_t r[4], uint32_t addr) {
    asm volatile("ldmatrix.sync.aligned.m8n8.x4.shared.b16 {%0,%1,%2,%3}, [%4];"
                 : "=r"(r[0]), "=r"(r[1]), "=r"(r[2]), "=r"(r[3]) : "r"(addr));
}

__device__ __forceinline__ void ldsm_x4_t(uint32_t r[4], uint32_t addr) {
    asm volatile("ldmatrix.sync.aligned.m8n8.x4.trans.shared.b16 {%0,%1,%2,%3}, [%4];"
                 : "=r"(r[0]), "=r"(r[1]), "=r"(r[2]), "=r"(r[3]) : "r"(addr));
}

__device__ __forceinline__ void mma_bf16(float c[4],
    uint32_t a0, uint32_t a1, uint32_t a2, uint32_t a3,
    uint32_t b0, uint32_t b1)
{
    asm volatile(
        "mma.sync.aligned.m16n8k16.row.col.f32.bf16.bf16.f32 "
        "{%0,%1,%2,%3}, {%4,%5,%6,%7}, {%8,%9}, {%0,%1,%2,%3};"
        : "+f"(c[0]), "+f"(c[1]), "+f"(c[2]), "+f"(c[3])
        : "r"(a0), "r"(a1), "r"(a2), "r"(a3), "r"(b0), "r"(b1));
}

// split fp32 pair -> packed bf16x2 hi and lo (residual).
// hi = {lo16: bf16(x), hi16: bf16(y)}; lo likewise for residuals.
__device__ __forceinline__ void split2(float x, float y, uint32_t& hi, uint32_t& lo)
{
    uint32_t h;
    asm("cvt.rn.bf16x2.f32 %0, %1, %2;" : "=r"(h) : "f"(y), "f"(x));
    float hx = __uint_as_float(h << 16);
    float hy = __uint_as_float(h & 0xffff0000u);
    float lx = x - hx, ly = y - hy;
    uint32_t l;
    asm("cvt.rn.bf16x2.f32 %0, %1, %2;" : "=r"(l) : "f"(ly), "f"(lx));
    hi = h; lo = l;
}

// convert 8 fp32 (two float4) -> uint4 of bf16-hi pairs and uint4 of bf16-lo pairs
__device__ __forceinline__ void cvt16(const float4& a, const float4& b,
                                      uint4& hi, uint4& lo)
{
    uint32_t h0,h1,h2,h3,l0,l1,l2,l3;
    split2(a.x, a.y, h0, l0); split2(a.z, a.w, h1, l1);
    split2(b.x, b.y, h2, l2); split2(b.z, b.w, h3, l3);
    hi = make_uint4(h0,h1,h2,h3);
    lo = make_uint4(l0,l1,l2,l3);
}

// ===========================================================================
// HMMA NT GEMM (structure unchanged from R4/R5, passing)
// ===========================================================================
#define LDA_B   80
#define OFF_AHI 0
#define OFF_ALO 10240
#define OFF_BHI 20480
#define OFF_BLO 30720
#define STAGE_B 40960
#define GEMM_SMEM (2 * STAGE_B)          // 81920 B

__global__ __launch_bounds__(256, 1) void gemm_tc(
    const float* __restrict__ A, const float* __restrict__ B,
    float* __restrict__ C)
{
    extern __shared__ char smc[];
    const uint32_t sbase = smem_to_u32(smc);
    const int tid  = threadIdx.x;
    const int lane = tid & 31;
    const int w    = tid >> 5;
    const int wm   = w >> 2;
    const int wn   = w & 3;
    const int bn = blockIdx.x * 128;
    const int bm = blockIdx.y * 128;

    float acc[4][4][4];
    #pragma unroll
    for (int i = 0; i < 4; i++)
        #pragma unroll
        for (int j = 0; j < 4; j++)
            #pragma unroll
            for (int q = 0; q < 4; q++) acc[i][j][q] = 0.f;

    float4 a_st[4], b_st[4];

    #pragma unroll
    for (int u = 0; u < 2; ++u) {
        int idx = tid + u * 256;
        int r = idx >> 2, kk = (idx & 3) << 3;
        const float4* pa = (const float4*)&A[(size_t)(bm + r) * GK + kk];
        a_st[2*u] = pa[0]; a_st[2*u+1] = pa[1];
        const float4* pb = (const float4*)&B[(size_t)(bn + r) * GK + kk];
        b_st[2*u] = pb[0]; b_st[2*u+1] = pb[1];
    }

    const int NCH = GK / 32;

    for (int it = 0; it < NCH; ++it) {
        const uint32_t stg = (uint32_t)(it & 1) * STAGE_B;

        #pragma unroll
        for (int u = 0; u < 2; ++u) {
            int idx = tid + u * 256;
            int r = idx >> 2, kk = (idx & 3) << 3;
            uint32_t off = (uint32_t)(r * LDA_B + kk * 2);
            uint4 hi, lo;
            cvt16(a_st[2*u], a_st[2*u+1], hi, lo);
            *(uint4*)(smc + stg + OFF_AHI + off) = hi;
            *(uint4*)(smc + stg + OFF_ALO + off) = lo;
            cvt16(b_st[2*u], b_st[2*u+1], hi, lo);
            *(uint4*)(smc + stg + OFF_BHI + off) = hi;
            *(uint4*)(smc + stg + OFF_BLO + off) = lo;
        }
        __syncthreads();

        if (it + 1 < NCH) {
            const int k0 = (it + 1) * 32;
            #pragma unroll
            for (int u = 0; u < 2; ++u) {
                int idx = tid + u * 256;
                int r = idx >> 2, kk = (idx & 3) << 3;
                const float4* pa = (const float4*)&A[(size_t)(bm + r) * GK + k0 + kk];
                a_st[2*u] = pa[0]; a_st[2*u+1] = pa[1];
                const float4* pb = (const float4*)&B[(size_t)(bn + r) * GK + k0 + kk];
                b_st[2*u] = pb[0]; b_st[2*u+1] = pb[1];
            }
        }

        const uint32_t sb = sbase + stg;
        #pragma unroll
        for (int ks = 0; ks < 2; ++ks) {
            uint32_t ah[4][4], al[4][4], bh[2][4], bl[2][4];
            const uint32_t kcol = (uint32_t)((ks * 16 + ((lane >> 4) << 3)) * 2);
            const int arow = wm * 64 + (lane & 15);
            #pragma unroll
            for (int ms = 0; ms < 4; ++ms) {
                uint32_t off = (uint32_t)((arow + ms * 16) * LDA_B) + kcol;
                ldsm_x4(ah[ms], sb + OFF_AHI + off);
                ldsm_x4(al[ms], sb + OFF_ALO + off);
            }
            const int brow = wn * 32 + (lane & 15);
            #pragma unroll
            for (int pr = 0; pr < 2; ++pr) {
                uint32_t off = (uint32_t)((brow + pr * 16) * LDA_B) + kcol;
                ldsm_x4(bh[pr], sb + OFF_BHI + off);
                ldsm_x4(bl[pr], sb + OFF_BLO + off);
            }
            #pragma unroll
            for (int ms = 0; ms < 4; ++ms)
                #pragma unroll
                for (int ns = 0; ns < 4; ++ns) {
                    const int pr = ns >> 1, od = ns & 1;
                    mma_bf16(acc[ms][ns], ah[ms][0], ah[ms][1], ah[ms][2], ah[ms][3],
                             bh[pr][od], bh[pr][od + 2]);
                    mma_bf16(acc[ms][ns], ah[ms][0], ah[ms][1], ah[ms][2], ah[ms][3],
                             bl[pr][od], bl[pr][od + 2]);
                    mma_bf16(acc[ms][ns], al[ms][0], al[ms][1], al[ms][2], al[ms][3],
                             bh[pr][od], bh[pr][od + 2]);
                }
        }
        __syncthreads();
    }

    #pragma unroll
    for (int ms = 0; ms < 4; ++ms) {
        const int row0 = bm + wm * 64 + ms * 16 + (lane >> 2);
        #pragma unroll
        for (int ns = 0; ns < 4; ++ns) {
            const int col = bn + wn * 32 + ns * 8 + (lane & 3) * 2;
            *(float2*)&C[(size_t)row0 * GN + col] =
                make_float2(acc[ms][ns][0], acc[ms][ns][1]);
            *(float2*)&C[(size_t)(row0 + 8) * GN + col] =
                make_float2(acc[ms][ns][2], acc[ms][ns][3]);
        }
    }
}

// ===========================================================================
// Tensor-core flash attention, software-pipelined.
// Block = 128 queries of one (b,h); 8 warps, warp owns 16 q rows.
// KV tiles of 64, double-buffered smem; next tile's K/V/mask LDGs are
// register-staged during the current tile's compute.
// ===========================================================================
#define FS_LD    144                   // smem row stride bytes (9*16)
#define FKLO     9216                  // K lo offset within buffer
#define FVHI     18432                 // V hi
#define FVLO     27648                 // V lo
#define KV_BUF   36864                 // bytes per KV buffer
#define FQ_HI    0                     // Q staging (reuses buffer 0+1 area)
#define FQ_LO    18432
#define FBIAS    (2 * KV_BUF)          // 73728; 64 floats per buffer
#define FA_SMEM  (FBIAS + 2 * 256)     // 74240 B

__global__ __launch_bounds__(256, 1) void flash_tc(
    const float* __restrict__ Q, const float* __restrict__ K,
    const float* __restrict__ V, const int* __restrict__ mask,
    float* __restrict__ O)
{
    extern __shared__ char smc[];
    const uint32_t sbase = smem_to_u32(smc);
    const int tid  = threadIdx.x;
    const int lane = tid & 31;
    const int w    = tid >> 5;
    const int q0 = blockIdx.x * 128;
    const int h  = blockIdx.y;
    const int b  = blockIdx.z;

    const size_t base = (size_t)b * SEQ * EMB + h * HDIM;
    const float* Qb = Q + base;
    const float* Kb = K + base;
    const float* Vb = V + base;
    const int* mb = mask + (size_t)b * SEQ;

    // ---- stage Q tile (128 x 64) as bf16 hi/lo in smem
    {
        const int row = tid >> 1;
        const int d0  = (tid & 1) * 32;
        const float4* pq = (const float4*)&Qb[(size_t)(q0 + row) * EMB + d0];
        #pragma unroll
        for (int sg = 0; sg < 4; ++sg) {
            uint4 hi, lo;
            cvt16(pq[2*sg], pq[2*sg+1], hi, lo);
            uint32_t off = (uint32_t)(row * FS_LD + d0 * 2 + sg * 16);
            *(uint4*)(smc + FQ_HI + off) = hi;
            *(uint4*)(smc + FQ_LO + off) = lo;
        }
    }
    __syncthreads();

    // ---- extract Q fragments (register-resident for whole KV loop)
    uint32_t qh[4][4], ql[4][4];
    #pragma unroll
    for (int ks = 0; ks < 4; ++ks) {
        uint32_t off = (uint32_t)((w * 16 + (lane & 15)) * FS_LD +
                                  (ks * 16 + ((lane >> 4) << 3)) * 2);
        ldsm_x4(qh[ks], sbase + FQ_HI + off);
        ldsm_x4(ql[ks], sbase + FQ_LO + off);
    }
    __syncthreads();   // Q fully extracted before buffers are overwritten

    float oacc[8][4];
    #pragma unroll
    for (int j = 0; j < 8; ++j)
        #pragma unroll
        for (int q = 0; q < 4; ++q) oacc[j][q] = 0.f;
    float mrow0 = -1e30f, mrow1 = -1e30f, lrow0 = 0.f, lrow1 = 0.f;

    // per-thread KV load mapping
    const int kvr = tid >> 2;
    const int d0  = (tid & 3) << 4;

    // ---- preload tile 0 into registers
    float4 kst[4], vst[4];
    int mst = 0;
    {
        const float4* pk = (const float4*)&Kb[(size_t)kvr * EMB + d0];
        const float4* pv = (const float4*)&Vb[(size_t)kvr * EMB + d0];
        #pragma unroll
        for (int g = 0; g < 4; ++g) { kst[g] = pk[g]; vst[g] = pv[g]; }
        if (tid < 64) mst = mb[tid];
    }

    for (int kv0 = 0; kv0 < SEQ; kv0 += 64) {
        const int bufi = (kv0 >> 6) & 1;
        const uint32_t bb = (uint32_t)bufi * KV_BUF;

        // ---- store staged tile -> smem[bufi]
        #pragma unroll
        for (int sg = 0; sg < 2; ++sg) {
            uint4 hi, lo;
            uint32_t off = bb + (uint32_t)(kvr * FS_LD + d0 * 2 + sg * 16);
            cvt16(kst[2*sg], kst[2*sg+1], hi, lo);
            *(uint4*)(smc + off)         = hi;   // K hi
            *(uint4*)(smc + FKLO + off)  = lo;   // K lo
            cvt16(vst[2*sg], vst[2*sg+1], hi, lo);
            *(uint4*)(smc + FVHI + off)  = hi;   // V hi
            *(uint4*)(smc + FVLO + off)  = lo;   // V lo
        }
        if (tid < 64)
            *(float*)(smc + FBIAS + bufi * 256 + tid * 4) = mst ? 0.f : -1e30f;
        __syncthreads();

        // ---- prefetch next tile into registers (overlaps compute below)
        if (kv0 + 64 < SEQ) {
            const float4* pk = (const float4*)&Kb[(size_t)(kv0 + 64 + kvr) * EMB + d0];
            const float4* pv = (const float4*)&Vb[(size_t)(kv0 + 64 + kvr) * EMB + d0];
            #pragma unroll
            for (int g = 0; g < 4; ++g) { kst[g] = pk[g]; vst[g] = pv[g]; }
            if (tid < 64) mst = mb[kv0 + 64 + tid];
        }

        const uint32_t sb = sbase + bb;

        // ---- S = Q K^T : 8 n-tiles of 8 kv, split-bf16 3-pass
        float s[8][4];
        #pragma unroll
        for (int j = 0; j < 8; ++j)
            #pragma unroll
            for (int q = 0; q < 4; ++q) s[j][q] = 0.f;

        #pragma unroll
        for (int pr = 0; pr < 4; ++pr) {
            #pragma unroll
            for (int ks = 0; ks < 4; ++ks) {
                uint32_t kh[4], kl[4];
                uint32_t off = (uint32_t)(((lane & 15) + pr * 16) * FS_LD +
                                          (ks * 16 + ((lane >> 4) << 3)) * 2);
                ldsm_x4(kh, sb + off);
                ldsm_x4(kl, sb + FKLO + off);
                #pragma unroll
                for (int od = 0; od < 2; ++od) {
                    const int j = pr * 2 + od;
                    mma_bf16(s[j], qh[ks][0], qh[ks][1], qh[ks][2], qh[ks][3],
                             kh[od], kh[od + 2]);
                    mma_bf16(s[j], qh[ks][0], qh[ks][1], qh[ks][2], qh[ks][3],
                             kl[od], kl[od + 2]);
                    mma_bf16(s[j], ql[ks][0], ql[ks][1], ql[ks][2], ql[ks][3],
                             kh[od], kh[od + 2]);
                }
            }
        }

        // ---- scale + mask bias
        const float scale = 0.125f;   // 1/sqrt(64)
        #pragma unroll
        for (int j = 0; j < 8; ++j) {
            float2 bs = *(float2*)(smc + FBIAS + bufi * 256 +
                                   (j * 8 + (lane & 3) * 2) * 4);
            s[j][0] = s[j][0] * scale + bs.x;
            s[j][1] = s[j][1] * scale + bs.y;
            s[j][2] = s[j][2] * scale + bs.x;
            s[j][3] = s[j][3] * scale + bs.y;
        }

        // ---- online softmax (rows live on quads: shfl_xor 1,2)
        float rm0 = -1e30f, rm1 = -1e30f;
        #pragma unroll
        for (int j = 0; j < 8; ++j) {
            rm0 = fmaxf(rm0, fmaxf(s[j][0], s[j][1]));
            rm1 = fmaxf(rm1, fmaxf(s[j][2], s[j][3]));
        }
        rm0 = fmaxf(rm0, __shfl_xor_sync(0xffffffffu, rm0, 1));
        rm0 = fmaxf(rm0, __shfl_xor_sync(0xffffffffu, rm0, 2));
        rm1 = fmaxf(rm1, __shfl_xor_sync(0xffffffffu, rm1, 1));
        rm1 = fmaxf(rm1, __shfl_xor_sync(0xffffffffu, rm1, 2));
        const float mn0 = fmaxf(mrow0, rm0);
        const float mn1 = fmaxf(mrow1, rm1);
        const float corr0 = __expf(mrow0 - mn0);
        const float corr1 = __expf(mrow1 - mn1);
        float sum0 = 0.f, sum1 = 0.f;
        #pragma unroll
        for (int j = 0; j < 8; ++j) {
            s[j][0] = __expf(s[j][0] - mn0); sum0 += s[j][0];
            s[j][1] = __expf(s[j][1] - mn0); sum0 += s[j][1];
            s[j][2] = __expf(s[j][2] - mn1); sum1 += s[j][2];
            s[j][3] = __expf(s[j][3] - mn1); sum1 += s[j][3];
        }
        sum0 += __shfl_xor_sync(0xffffffffu, sum0, 1);
        sum0 += __shfl_xor_sync(0xffffffffu, sum0, 2);
        sum1 += __shfl_xor_sync(0xffffffffu, sum1, 1);
        sum1 += __shfl_xor_sync(0xffffffffu, sum1, 2);
        lrow0 = lrow0 * corr0 + sum0;
        lrow1 = lrow1 * corr1 + sum1;
        mrow0 = mn0; mrow1 = mn1;
        #pragma unroll
        for (int j = 0; j < 8; ++j) {
            oacc[j][0] *= corr0; oacc[j][1] *= corr0;
            oacc[j][2] *= corr1; oacc[j][3] *= corr1;
        }

        // ---- O += P V : P fragments from S registers; V via ldmatrix.trans
        #pragma unroll
        for (int kk = 0; kk < 4; ++kk) {
            uint32_t ah[4], al[4];
            split2(s[2*kk][0],   s[2*kk][1],   ah[0], al[0]);
            split2(s[2*kk][2],   s[2*kk][3],   ah[1], al[1]);
            split2(s[2*kk+1][0], s[2*kk+1][1], ah[2], al[2]);
            split2(s[2*kk+1][2], s[2*kk+1][3], ah[3], al[3]);
            #pragma unroll
            for (int g = 0; g < 4; ++g) {
                uint32_t vh[4], vl[4];
                uint32_t voff = (uint32_t)(
                    (kk * 16 + ((lane >> 4) << 3) + (lane & 7)) * FS_LD +
                    g * 32 + ((lane >> 3) & 1) * 16);
                ldsm_x4_t(vh, sb + FVHI + voff);
                ldsm_x4_t(vl, sb + FVLO + voff);
                #pragma unroll
                for (int od = 0; od < 2; ++od) {
                    const int j = g * 2 + od;
                    mma_bf16(oacc[j], ah[0], ah[1], ah[2], ah[3], vh[od], vh[od + 2]);
                    mma_bf16(oacc[j], ah[0], ah[1], ah[2], ah[3], vl[od], vl[od + 2]);
                    mma_bf16(oacc[j], al[0], al[1], al[2], al[3], vh[od], vh[od + 2]);
                }
            }
        }
    }

    // ---- normalize + write context
    const float inv0 = 1.f / lrow0;
    const float inv1 = 1.f / lrow1;
    float* Ob = O + base;
    const int r0 = q0 + w * 16 + (lane >> 2);
    #pragma unroll
    for (int j = 0; j < 8; ++j) {
        const int col = j * 8 + (lane & 3) * 2;
        *(float2*)&Ob[(size_t)r0 * EMB + col] =
            make_float2(oacc[j][0] * inv0, oacc[j][1] * inv0);
        *(float2*)&Ob[(size_t)(r0 + 8) * EMB + col] =
            make_float2(oacc[j][2] * inv1, oacc[j][3] * inv1);
    }
}

// ---------------------------------------------------------------------------
// Launch
// ---------------------------------------------------------------------------
extern "C" void kernel_launch(void* const* d_in, const int* in_sizes, int n_in,
                              void* d_out, int out_size)
{
    const float* x   = (const float*)d_in[0];
    const int*   am  = (const int*)d_in[1];   // bool mask materialized as int32
    const float* Wq  = (const float*)d_in[2];
    const float* Wk  = (const float*)d_in[3];
    const float* Wv  = (const float*)d_in[4];
    const float* Wo  = (const float*)d_in[5];
    float* out       = (float*)d_out;

    float *Qp, *Kp, *Vp, *Cp;
    cudaGetSymbolAddress((void**)&Qp, g_Q);
    cudaGetSymbolAddress((void**)&Kp, g_K);
    cudaGetSymbolAddress((void**)&Vp, g_V);
    cudaGetSymbolAddress((void**)&Cp, g_C);

    cudaFuncSetAttribute(gemm_tc, cudaFuncAttributeMaxDynamicSharedMemorySize,
                         GEMM_SMEM);
    cudaFuncSetAttribute(flash_tc, cudaFuncAttributeMaxDynamicSharedMemorySize,
                         FA_SMEM);

    dim3 gemm_grid(GN / 128, ROWS / 128);    // (8, 32)
    gemm_tc<<<gemm_grid, 256, GEMM_SMEM>>>(x, Wq, Qp);
    gemm_tc<<<gemm_grid, 256, GEMM_SMEM>>>(x, Wk, Kp);
    gemm_tc<<<gemm_grid, 256, GEMM_SMEM>>>(x, Wv, Vp);

    dim3 fa_grid(SEQ / 128, HEADS, BATCH);   // (16, 16, 2)
    flash_tc<<<fa_grid, 256, FA_SMEM>>>(Qp, Kp, Vp, am, Cp);

    gemm_tc<<<gemm_grid, 256, GEMM_SMEM>>>(Cp, Wo, out);
}